// round 16
// baseline (speedup 1.0000x reference)
#include <cuda_runtime.h>
#include <cuda_fp16.h>
#include <math.h>
#include <stdint.h>

#define Bsz 2
#define Tsz 2048
#define Csz 1024
#define NH 16
#define NKV 4
#define HD 64
#define Mrows (Bsz*Tsz)      // 4096
#define KVC (NKV*HD)         // 256
#define KVS (2*KVC)          // 512 (fused K|V width)
#define QB 64                // q rows per attention CTA

// Scratch (device globals: no allocation allowed)
__device__ __half g_xh  [Mrows*Csz];
__device__ __half g_wqh [Csz*Csz];
__device__ __half g_wkvh[Csz*KVS];
__device__ __half g_woh [Csz*Csz];
__device__ __half g_q   [Mrows*Csz];   // fp16 Q, RoPE'd, pre-scaled 1/8
__device__ __half g_k   [Mrows*KVC];   // fp16 K, RoPE'd
__device__ __half g_v   [Mrows*KVC];   // fp16 V
__device__ __half g_ao  [Mrows*Csz];   // fp16 attention output

// Streams/events created at static-init time (R14-proven).
struct StrHolder {
    cudaStream_t s1, s2;
    cudaEvent_t eA, e1, e2;
    StrHolder() {
        cudaStreamCreateWithFlags(&s1, cudaStreamNonBlocking);
        cudaStreamCreateWithFlags(&s2, cudaStreamNonBlocking);
        cudaEventCreateWithFlags(&eA, cudaEventDisableTiming);
        cudaEventCreateWithFlags(&e1, cudaEventDisableTiming);
        cudaEventCreateWithFlags(&e2, cudaEventDisableTiming);
    }
};
static StrHolder g_str;

__device__ __forceinline__ void mma_f16(float c[4], const uint32_t a[4], const uint32_t b[2]) {
    asm volatile(
        "mma.sync.aligned.m16n8k16.row.col.f32.f16.f16.f32 "
        "{%0,%1,%2,%3}, {%4,%5,%6,%7}, {%8,%9}, {%0,%1,%2,%3};\n"
        : "+f"(c[0]), "+f"(c[1]), "+f"(c[2]), "+f"(c[3])
        : "r"(a[0]), "r"(a[1]), "r"(a[2]), "r"(a[3]), "r"(b[0]), "r"(b[1]));
}

__device__ __forceinline__ uint32_t packh2(float a, float b) {
    __half2 h = __floats2half2_rn(a, b);
    return *(uint32_t*)&h;
}

#define LDSM4(r0, r1, r2, r3, addr) \
    asm volatile("ldmatrix.sync.aligned.m8n8.x4.shared.b16 {%0,%1,%2,%3}, [%4];" \
        : "=r"(r0), "=r"(r1), "=r"(r2), "=r"(r3) : "r"(addr))

#define LDSM4T(r0, r1, r2, r3, addr) \
    asm volatile("ldmatrix.sync.aligned.m8n8.x4.trans.shared.b16 {%0,%1,%2,%3}, [%4];" \
        : "=r"(r0), "=r"(r1), "=r"(r2), "=r"(r3) : "r"(addr))

#define CP16(dst, src) \
    asm volatile("cp.async.cg.shared.global [%0], [%1], 16;\n" :: "r"(dst), "l"(src))
#define CP_COMMIT() asm volatile("cp.async.commit_group;\n")
#define CP_WAIT0()  asm volatile("cp.async.wait_group 0;\n" ::: "memory")
#define CP_WAIT1()  asm volatile("cp.async.wait_group 1;\n" ::: "memory")

// ---------------------------------------------------------------------------
__global__ void f2h(const float* __restrict__ in, __half* __restrict__ out_, int n4)
{
    int i = blockIdx.x * blockDim.x + threadIdx.x;
    if (i < n4) {
        float4 t = ((const float4*)in)[i];
        ((uint2*)out_)[i] = make_uint2(packh2(t.x, t.y), packh2(t.z, t.w));
    }
}

__global__ void f2h_s(const float* __restrict__ in, __half* __restrict__ out_,
                      int n4, int off)
{
    int i = blockIdx.x * blockDim.x + threadIdx.x;
    if (i < n4) {
        float4 t = ((const float4*)in)[i];
        int row = i >> 6, col4 = i & 63;
        ((uint2*)out_)[row * (KVS/4) + (off >> 2) + col4] =
            make_uint2(packh2(t.x, t.y), packh2(t.z, t.w));
    }
}

// ---------------------------------------------------------------------------
// Fused K|V projection GEMM, 3-stage cp.async pipeline.
// ---------------------------------------------------------------------------
__global__ __launch_bounds__(256)
void gemm_kv(const __half* __restrict__ A, const __half* __restrict__ W,
             const float* __restrict__ b_k, const float* __restrict__ b_v,
             __half* __restrict__ Kout, __half* __restrict__ Vout, int M, int K)
{
    __shared__ uint32_t As[3][128][20];
    __shared__ uint32_t Bs[3][32][36];

    int tid = threadIdx.x;
    int lane = tid & 31, w = tid >> 5;
    int g = lane >> 2, tg = lane & 3;
    int wm = (w & 3) * 32, wn = (w >> 2) * 32;
    int m0 = blockIdx.y * 128, n0 = blockIdx.x * 64;

    int la  = lane & 15;
    int ha  = (lane >> 4) * 4;
    int lbk = (lane & 7) + ((lane >> 3) & 1) * 8;
    int hbn = (lane >> 4) * 4;

    uint32_t asb = (uint32_t)__cvta_generic_to_shared(&As[0][0][0]);
    uint32_t bsb = (uint32_t)__cvta_generic_to_shared(&Bs[0][0][0]);

    int ar = tid >> 2, ac4 = tid & 3;
    int br = tid >> 3, bc4 = tid & 7;

    auto issue = [&](int k0, int buf) {
        uint32_t ad = asb + buf * 128 * 20 * 4;
        uint32_t bd = bsb + buf * 32 * 36 * 4;
        CP16(ad + (ar * 20 + ac4 * 4) * 4,         A + (size_t)(m0 + ar) * K + k0 + ac4 * 8);
        CP16(ad + ((ar + 64) * 20 + ac4 * 4) * 4,  A + (size_t)(m0 + ar + 64) * K + k0 + ac4 * 8);
        CP16(bd + (br * 36 + bc4 * 4) * 4,         W + (size_t)(k0 + br) * KVS + n0 + bc4 * 8);
        CP_COMMIT();
    };

    float acc[2][4][4] = {};

    int niter = K / 32;
    issue(0, 0);
    issue(32, 1);

    for (int i = 0; i < niter; i++) {
        int cur = i % 3;
        if (i + 1 < niter) CP_WAIT1(); else CP_WAIT0();
        __syncthreads();
        if (i + 2 < niter) issue((i + 2) * 32, (i + 2) % 3);

        uint32_t aoff = asb + cur * 128 * 20 * 4;
        uint32_t boff = bsb + cur * 32 * 36 * 4;

#pragma unroll
        for (int ks = 0; ks < 2; ks++) {
            uint32_t af[2][4], bf[4][2];
#pragma unroll
            for (int mt = 0; mt < 2; mt++) {
                uint32_t addr = aoff + ((wm + mt*16 + la) * 20 + ks*8 + ha) * 4;
                LDSM4(af[mt][0], af[mt][1], af[mt][2], af[mt][3], addr);
            }
#pragma unroll
            for (int ntp = 0; ntp < 2; ntp++) {
                uint32_t addr = boff + ((ks*16 + lbk) * 36 + wn/2 + ntp*8 + hbn) * 4;
                LDSM4T(bf[2*ntp][0], bf[2*ntp][1], bf[2*ntp+1][0], bf[2*ntp+1][1], addr);
            }
#pragma unroll
            for (int mt = 0; mt < 2; mt++)
#pragma unroll
                for (int nt = 0; nt < 4; nt++)
                    mma_f16(acc[mt][nt], af[mt], bf[nt]);
        }
    }

    bool isk = (n0 < KVC);
    const float* biasp = isk ? b_k : b_v;
    __half* Cp = isk ? Kout : Vout;
    int cbase = isk ? n0 : n0 - KVC;

#pragma unroll
    for (int mt = 0; mt < 2; mt++) {
        int r0 = m0 + wm + mt * 16 + g;
#pragma unroll
        for (int nt = 0; nt < 4; nt++) {
            int cl = cbase + wn + nt * 8 + tg * 2;
            float2 bb = *(const float2*)(biasp + cl);
            float2 v0 = make_float2(acc[mt][nt][0] + bb.x, acc[mt][nt][1] + bb.y);
            float2 v1 = make_float2(acc[mt][nt][2] + bb.x, acc[mt][nt][3] + bb.y);
            if (isk) {
                int pair = (cl & (HD - 1)) >> 1;
                float inv = powf(10000.0f, -(float)(2 * pair) / (float)HD);
                float sn0, cs0, sn1, cs1;
                sincosf((float)(r0 & (Tsz - 1)) * inv, &sn0, &cs0);
                sincosf((float)((r0 + 8) & (Tsz - 1)) * inv, &sn1, &cs1);
                float e0 = v0.x, o0 = v0.y;
                v0.x = e0 * cs0 - o0 * sn0;  v0.y = e0 * sn0 + o0 * cs0;
                float e1 = v1.x, o1 = v1.y;
                v1.x = e1 * cs1 - o1 * sn1;  v1.y = e1 * sn1 + o1 * cs1;
            }
            *(uint32_t*)(Cp + (size_t)r0 * KVC + cl)       = packh2(v0.x, v0.y);
            *(uint32_t*)(Cp + (size_t)(r0 + 8) * KVC + cl) = packh2(v1.x, v1.y);
        }
    }
}

// ---------------------------------------------------------------------------
// WIDE fp16 GEMM, CTA tile 128x128, 3-stage cp.async pipeline.
// ---------------------------------------------------------------------------
template<bool DO_ROPE, bool HALF_OUT>
__global__ __launch_bounds__(256, 2)
void gemm_w(const __half* __restrict__ A, const __half* __restrict__ W,
            const float* __restrict__ bias, void* __restrict__ Cout,
            int M, int K, int N, float oscale)
{
    __shared__ uint32_t As[3][128][20];
    __shared__ uint32_t Bs[3][32][68];

    int tid = threadIdx.x;
    int lane = tid & 31, w = tid >> 5;
    int g = lane >> 2, tg = lane & 3;
    int wm = (w & 3) * 32, wn = (w >> 2) * 64;
    int m0 = blockIdx.y * 128, n0 = blockIdx.x * 128;

    int la  = lane & 15;
    int ha  = (lane >> 4) * 4;
    int lbk = (lane & 7) + ((lane >> 3) & 1) * 8;
    int hbn = (lane >> 4) * 4;

    uint32_t asb = (uint32_t)__cvta_generic_to_shared(&As[0][0][0]);
    uint32_t bsb = (uint32_t)__cvta_generic_to_shared(&Bs[0][0][0]);

    int ar = tid >> 2, ac4 = tid & 3;
    int br = tid >> 4, bc4 = tid & 15;

    auto issue = [&](int k0, int buf) {
        uint32_t ad = asb + buf * 128 * 20 * 4;
        uint32_t bd = bsb + buf * 32 * 68 * 4;
        CP16(ad + (ar * 20 + ac4 * 4) * 4,          A + (size_t)(m0 + ar) * K + k0 + ac4 * 8);
        CP16(ad + ((ar + 64) * 20 + ac4 * 4) * 4,   A + (size_t)(m0 + ar + 64) * K + k0 + ac4 * 8);
        CP16(bd + (br * 68 + bc4 * 4) * 4,          W + (size_t)(k0 + br) * N + n0 + bc4 * 8);
        CP16(bd + ((br + 16) * 68 + bc4 * 4) * 4,   W + (size_t)(k0 + br + 16) * N + n0 + bc4 * 8);
        CP_COMMIT();
    };

    float acc[2][8][4] = {};

    int niter = K / 32;
    issue(0, 0);
    issue(32, 1);

    for (int i = 0; i < niter; i++) {
        int cur = i % 3;
        if (i + 1 < niter) CP_WAIT1(); else CP_WAIT0();
        __syncthreads();
        if (i + 2 < niter) issue((i + 2) * 32, (i + 2) % 3);

        uint32_t aoff = asb + cur * 128 * 20 * 4;
        uint32_t boff = bsb + cur * 32 * 68 * 4;

#pragma unroll
        for (int ks = 0; ks < 2; ks++) {
            uint32_t af[2][4], bf[8][2];
#pragma unroll
            for (int mt = 0; mt < 2; mt++) {
                uint32_t addr = aoff + ((wm + mt*16 + la) * 20 + ks*8 + ha) * 4;
                LDSM4(af[mt][0], af[mt][1], af[mt][2], af[mt][3], addr);
            }
#pragma unroll
            for (int ntp = 0; ntp < 4; ntp++) {
                uint32_t addr = boff + ((ks*16 + lbk) * 68 + wn/2 + ntp*8 + hbn) * 4;
                LDSM4T(bf[2*ntp][0], bf[2*ntp][1], bf[2*ntp+1][0], bf[2*ntp+1][1], addr);
            }
#pragma unroll
            for (int mt = 0; mt < 2; mt++)
#pragma unroll
                for (int nt = 0; nt < 8; nt++)
                    mma_f16(acc[mt][nt], af[mt], bf[nt]);
        }
    }

#pragma unroll
    for (int mt = 0; mt < 2; mt++) {
        int r0 = m0 + wm + mt * 16 + g;
#pragma unroll
        for (int nt = 0; nt < 8; nt++) {
            int c = n0 + wn + nt * 8 + tg * 2;
            float2 bb = *(const float2*)(bias + c);
            float2 v0 = make_float2(acc[mt][nt][0] + bb.x, acc[mt][nt][1] + bb.y);
            float2 v1 = make_float2(acc[mt][nt][2] + bb.x, acc[mt][nt][3] + bb.y);
            if (DO_ROPE) {
                int pair = (c & (HD - 1)) >> 1;
                float inv = powf(10000.0f, -(float)(2 * pair) / (float)HD);
                float sn0, cs0, sn1, cs1;
                sincosf((float)(r0 & (Tsz - 1)) * inv, &sn0, &cs0);
                sincosf((float)((r0 + 8) & (Tsz - 1)) * inv, &sn1, &cs1);
                float e0 = v0.x, o0 = v0.y;
                v0.x = e0 * cs0 - o0 * sn0;  v0.y = e0 * sn0 + o0 * cs0;
                float e1 = v1.x, o1 = v1.y;
                v1.x = e1 * cs1 - o1 * sn1;  v1.y = e1 * sn1 + o1 * cs1;
            }
            v0.x *= oscale; v0.y *= oscale; v1.x *= oscale; v1.y *= oscale;
            if (HALF_OUT) {
                __half* C = (__half*)Cout;
                *(uint32_t*)(C + (size_t)r0 * N + c)       = packh2(v0.x, v0.y);
                *(uint32_t*)(C + (size_t)(r0 + 8) * N + c) = packh2(v1.x, v1.y);
            } else {
                float* C = (float*)Cout;
                *(float2*)(C + (size_t)r0 * N + c)       = v0;
                *(float2*)(C + (size_t)(r0 + 8) * N + c) = v1;
            }
        }
    }
}

// ---------------------------------------------------------------------------
// Flash attention v4 (R15-proven) with 3-stage K/V cp.async pipeline.
// CTA: 64 q-rows x 1 head, 8 warps = 4(m,16 rows)x2(n,32 keys).
// ---------------------------------------------------------------------------
__global__ __launch_bounds__(256, 2)
void attn_f16(const __half* __restrict__ q, const __half* __restrict__ k,
              const __half* __restrict__ v, __half* __restrict__ o)
{
    extern __shared__ uint32_t smu[];
    uint32_t* Qs = smu;                    // [64][36]
    uint32_t* Ks = smu + 64*36;            // [3][64][36] row=key
    uint32_t* Vs = smu + 64*36 + 3*64*36;  // [3][64][36] row=key

    int b  = blockIdx.z;
    int h  = blockIdx.y;
    int qb = gridDim.x - 1 - blockIdx.x;   // heavy blocks first
    int q0 = qb * QB;
    int kvh = h >> 2;

    int tid = threadIdx.x;
    int lane = tid & 31, w = tid >> 5;
    int g = lane >> 2, tg = lane & 3;
    int wm = (w >> 1) * 16;    // warp row origin (0,16,32,48)
    int wn = w & 1;            // key half

    int la  = lane & 15;
    int ha  = (lane >> 4) * 4;
    int lb  = (lane & 7) + (lane >> 4) * 8;
    int hb  = ((lane >> 3) & 1) * 4;
    int lbk = (lane & 7) + ((lane >> 3) & 1) * 8;
    int hbn = (lane >> 4) * 4;

    uint32_t qsb = (uint32_t)__cvta_generic_to_shared(Qs);
    uint32_t ksb = (uint32_t)__cvta_generic_to_shared(Ks);
    uint32_t vsb = (uint32_t)__cvta_generic_to_shared(Vs);

    // Q tile via cp.async (own group; drains under the same wait accounting)
    {
        const __half* qbase = q + (size_t)(b * Tsz + q0) * Csz + h * HD;
#pragma unroll
        for (int p = 0; p < 2; p++) {
            int idx = tid + p * 256;
            int r = idx >> 3, c4 = idx & 7;
            CP16(qsb + (r * 36 + c4 * 4) * 4, qbase + (size_t)r * Csz + c4 * 8);
        }
        CP_COMMIT();
    }

    float mrun[2], lrun[2];
    float oacc[8][4] = {};
#pragma unroll
    for (int ri = 0; ri < 2; ri++) { mrun[ri] = -1e30f; lrun[ri] = 0.f; }

    auto issue_kv = [&](int kb, int buf) {
        const __half* kp = k + (size_t)(b * Tsz + kb * 64) * KVC + kvh * HD;
        const __half* vp = v + (size_t)(b * Tsz + kb * 64) * KVC + kvh * HD;
        uint32_t kdst = ksb + buf * 64 * 36 * 4;
        uint32_t vdst = vsb + buf * 64 * 36 * 4;
#pragma unroll
        for (int p = 0; p < 2; p++) {
            int idx = tid + p * 256;
            int key = idx >> 3, c4 = idx & 7;
            CP16(kdst + (key * 36 + c4 * 4) * 4, kp + (size_t)key * KVC + c4 * 8);
            CP16(vdst + (key * 36 + c4 * 4) * 4, vp + (size_t)key * KVC + c4 * 8);
        }
        CP_COMMIT();
    };

    issue_kv(0, 0);
    if (qb > 0) issue_kv(1, 1);

    for (int kb = 0; kb <= qb; kb++) {
        int cur = kb % 3;
        if (kb < qb) CP_WAIT1(); else CP_WAIT0();
        __syncthreads();   // the ONLY sync per tile
        if (kb + 2 <= qb) issue_kv(kb + 2, (kb + 2) % 3);

        uint32_t koff = ksb + cur * 64 * 36 * 4;
        uint32_t voff = vsb + cur * 64 * 36 * 4;

        // S = Q K^T : 16 rows x 32 keys (warp's half)
        float s[4][4] = {};
#pragma unroll
        for (int ks = 0; ks < 4; ks++) {
            uint32_t af[4], bf[4][2];
            {
                uint32_t addr = qsb + ((wm + la) * 36 + ks*8 + ha) * 4;
                LDSM4(af[0], af[1], af[2], af[3], addr);
            }
#pragma unroll
            for (int ntp = 0; ntp < 2; ntp++) {
                uint32_t addr = koff + ((wn*32 + ntp*16 + lb) * 36 + ks*8 + hb) * 4;
                LDSM4(bf[2*ntp][0], bf[2*ntp][1], bf[2*ntp+1][0], bf[2*ntp+1][1], addr);
            }
#pragma unroll
            for (int nt = 0; nt < 4; nt++)
                mma_f16(s[nt], af, bf[nt]);
        }

        // causal mask (diagonal tile only)
        if (kb == qb) {
            int row0 = q0 + wm + g;
#pragma unroll
            for (int nt = 0; nt < 4; nt++) {
                int col = kb * 64 + wn * 32 + nt * 8 + 2 * tg;
                if (col     > row0    ) s[nt][0] = -1e30f;
                if (col + 1 > row0    ) s[nt][1] = -1e30f;
                if (col     > row0 + 8) s[nt][2] = -1e30f;
                if (col + 1 > row0 + 8) s[nt][3] = -1e30f;
            }
        }

        // warp-local streaming softmax over this half's 32 keys
#pragma unroll
        for (int ri = 0; ri < 2; ri++) {
            float mx = -1e30f;
#pragma unroll
            for (int nt = 0; nt < 4; nt++) {
                mx = fmaxf(mx, s[nt][2*ri]);
                mx = fmaxf(mx, s[nt][2*ri+1]);
            }
            mx = fmaxf(mx, __shfl_xor_sync(0xffffffffu, mx, 1));
            mx = fmaxf(mx, __shfl_xor_sync(0xffffffffu, mx, 2));
            float mnew = fmaxf(mrun[ri], mx);
            float corr = __expf(mrun[ri] - mnew);
            float sum = 0.f;
#pragma unroll
            for (int nt = 0; nt < 4; nt++) {
                float p0 = __expf(s[nt][2*ri]   - mnew);
                float p1 = __expf(s[nt][2*ri+1] - mnew);
                s[nt][2*ri] = p0; s[nt][2*ri+1] = p1;
                sum += p0 + p1;
            }
            sum += __shfl_xor_sync(0xffffffffu, sum, 1);
            sum += __shfl_xor_sync(0xffffffffu, sum, 2);
            lrun[ri] = lrun[ri] * corr + sum;
            mrun[ri] = mnew;
#pragma unroll
            for (int nt = 0; nt < 8; nt++) {
                oacc[nt][2*ri]   *= corr;
                oacc[nt][2*ri+1] *= corr;
            }
        }

        // O_partial += P V : P in registers; V via ldmatrix.trans
#pragma unroll
        for (int ks = 0; ks < 2; ks++) {
            uint32_t af[4], bf[8][2];
            af[0] = packh2(s[2*ks  ][0], s[2*ks  ][1]);
            af[1] = packh2(s[2*ks  ][2], s[2*ks  ][3]);
            af[2] = packh2(s[2*ks+1][0], s[2*ks+1][1]);
            af[3] = packh2(s[2*ks+1][2], s[2*ks+1][3]);
#pragma unroll
            for (int ntp = 0; ntp < 4; ntp++) {
                uint32_t addr = voff + ((wn*32 + ks*16 + lbk) * 36 + ntp*8 + hbn) * 4;
                LDSM4T(bf[2*ntp][0], bf[2*ntp][1], bf[2*ntp+1][0], bf[2*ntp+1][1], addr);
            }
#pragma unroll
            for (int nt = 0; nt < 8; nt++)
                mma_f16(oacc[nt], af, bf[nt]);
        }
    }

    // ---- final cross-half merge (once) ----
    __syncthreads();                        // loop done; reuse smem
    float*  Osm = (float*)smu;              // [64][68]
    float2* ml  = (float2*)(smu + 64*68);   // [64]

    if (wn == 0) {
#pragma unroll
        for (int ri = 0; ri < 2; ri++) {
            int rl = wm + ri*8 + g;
            if (tg == 0) ml[rl] = make_float2(mrun[ri], lrun[ri]);
#pragma unroll
            for (int nt = 0; nt < 8; nt++)
                *(float2*)&Osm[rl * 68 + nt*8 + 2*tg] =
                    make_float2(oacc[nt][2*ri], oacc[nt][2*ri+1]);
        }
    }
    __syncthreads();

    if (wn == 1) {
        __half* obase = o + (size_t)(b * Tsz + q0) * Csz + h * HD;
#pragma unroll
        for (int ri = 0; ri < 2; ri++) {
            int rl = wm + ri*8 + g;
            float2 other = ml[rl];
            float mnew = fmaxf(mrun[ri], other.x);
            float c1 = __expf(mrun[ri] - mnew);
            float c0 = __expf(other.x  - mnew);
            float l = lrun[ri] * c1 + other.y * c0;
            float inv = 1.0f / l;
#pragma unroll
            for (int nt = 0; nt < 8; nt++) {
                float2 o0 = *(float2*)&Osm[rl * 68 + nt*8 + 2*tg];
                float r0 = (oacc[nt][2*ri]   * c1 + o0.x * c0) * inv;
                float r1 = (oacc[nt][2*ri+1] * c1 + o0.y * c0) * inv;
                *(uint32_t*)(obase + (size_t)rl * Csz + nt*8 + 2*tg) = packh2(r0, r1);
            }
        }
    }
}

// ---------------------------------------------------------------------------
extern "C" void kernel_launch(void* const* d_in, const int* in_sizes, int n_in,
                              void* d_out, int out_size)
{
    const float* x   = (const float*)d_in[0];
    const float* w_q = (const float*)d_in[1];
    const float* b_q = (const float*)d_in[2];
    const float* w_k = (const float*)d_in[3];
    const float* b_k = (const float*)d_in[4];
    const float* w_v = (const float*)d_in[5];
    const float* b_v = (const float*)d_in[6];
    const float* w_o = (const float*)d_in[7];
    const float* b_o = (const float*)d_in[8];
    float* out = (float*)d_out;

    __half *xh, *wqh, *wkvh, *woh, *q, *k, *v, *ao;
    cudaGetSymbolAddress((void**)&xh,   g_xh);
    cudaGetSymbolAddress((void**)&wqh,  g_wqh);
    cudaGetSymbolAddress((void**)&wkvh, g_wkvh);
    cudaGetSymbolAddress((void**)&woh,  g_woh);
    cudaGetSymbolAddress((void**)&q,    g_q);
    cudaGetSymbolAddress((void**)&k,    g_k);
    cudaGetSymbolAddress((void**)&v,    g_v);
    cudaGetSymbolAddress((void**)&ao,   g_ao);

    cudaStream_t s1 = g_str.s1, s2 = g_str.s2;

    // legacy: convert x, then fork
    f2h<<<(Mrows*Csz/4 + 255)/256, 256>>>(x, xh, Mrows*Csz/4);
    cudaEventRecord(g_str.eA, 0);

    // branch 1: Q projection
    cudaStreamWaitEvent(s1, g_str.eA, 0);
    f2h<<<(Csz*Csz/4 + 255)/256, 256, 0, s1>>>(w_q, wqh, Csz*Csz/4);
    gemm_w<true , true ><<<dim3(Csz/128, Mrows/128), 256, 0, s1>>>(
        xh, wqh, b_q, q, Mrows, Csz, Csz, 0.125f);
    cudaEventRecord(g_str.e1, s1);

    // branch 2: fused K|V projection
    cudaStreamWaitEvent(s2, g_str.eA, 0);
    f2h_s<<<(Csz*KVC/4 + 255)/256, 256, 0, s2>>>(w_k, wkvh, Csz*KVC/4, 0);
    f2h_s<<<(Csz*KVC/4 + 255)/256, 256, 0, s2>>>(w_v, wkvh, Csz*KVC/4, KVC);
    gemm_kv<<<dim3(KVS/64, Mrows/128), 256, 0, s2>>>(
        xh, wkvh, b_k, b_v, k, v, Mrows, Csz);
    cudaEventRecord(g_str.e2, s2);

    // legacy (concurrent): convert O weights
    f2h<<<(Csz*Csz/4 + 255)/256, 256>>>(w_o, woh, Csz*Csz/4);

    // join
    cudaStreamWaitEvent(0, g_str.e1, 0);
    cudaStreamWaitEvent(0, g_str.e2, 0);

    // flash attention v4, 3-stage K/V pipeline
    {
        int smem = (64 + 3*64 + 3*64) * 36 * 4;   // 64512
        cudaFuncSetAttribute(attn_f16, cudaFuncAttributeMaxDynamicSharedMemorySize, smem);
        attn_f16<<<dim3(Tsz/QB, NH, Bsz), 256, smem>>>(q, k, v, ao);
    }

    // output projection (wide gemm, fp32 out)
    gemm_w<false, false><<<dim3(Csz/128, Mrows/128), 256>>>(ao, woh, b_o, out, Mrows, Csz, Csz, 1.0f);
}

// round 17
// speedup vs baseline: 1.0945x; 1.0945x over previous
#include <cuda_runtime.h>
#include <cuda_fp16.h>
#include <math.h>
#include <stdint.h>

#define Bsz 2
#define Tsz 2048
#define Csz 1024
#define NH 16
#define NKV 4
#define HD 64
#define Mrows (Bsz*Tsz)      // 4096
#define KVC (NKV*HD)         // 256
#define KVS (2*KVC)          // 512 (fused K|V width)
#define QB 64                // q rows per attention CTA

// Scratch (device globals: no allocation allowed)
__device__ __half g_xh  [Mrows*Csz];
__device__ __half g_wqh [Csz*Csz];
__device__ __half g_wkvh[Csz*KVS];
__device__ __half g_woh [Csz*Csz];
__device__ __half g_q   [Mrows*Csz];   // fp16 Q, RoPE'd, pre-scaled 1/8
__device__ __half g_k   [Mrows*KVC];   // fp16 K, RoPE'd
__device__ __half g_v   [Mrows*KVC];   // fp16 V
__device__ __half g_ao  [Mrows*Csz];   // fp16 attention output

// Streams/events created at static-init time (R14-proven pattern).
struct StrHolder {
    cudaStream_t s1, s2;
    cudaEvent_t eA, e1, e2, eW, e3;
    StrHolder() {
        cudaStreamCreateWithFlags(&s1, cudaStreamNonBlocking);
        cudaStreamCreateWithFlags(&s2, cudaStreamNonBlocking);
        cudaEventCreateWithFlags(&eA, cudaEventDisableTiming);
        cudaEventCreateWithFlags(&e1, cudaEventDisableTiming);
        cudaEventCreateWithFlags(&e2, cudaEventDisableTiming);
        cudaEventCreateWithFlags(&eW, cudaEventDisableTiming);
        cudaEventCreateWithFlags(&e3, cudaEventDisableTiming);
    }
};
static StrHolder g_str;

__device__ __forceinline__ void mma_f16(float c[4], const uint32_t a[4], const uint32_t b[2]) {
    asm volatile(
        "mma.sync.aligned.m16n8k16.row.col.f32.f16.f16.f32 "
        "{%0,%1,%2,%3}, {%4,%5,%6,%7}, {%8,%9}, {%0,%1,%2,%3};\n"
        : "+f"(c[0]), "+f"(c[1]), "+f"(c[2]), "+f"(c[3])
        : "r"(a[0]), "r"(a[1]), "r"(a[2]), "r"(a[3]), "r"(b[0]), "r"(b[1]));
}

__device__ __forceinline__ uint32_t packh2(float a, float b) {
    __half2 h = __floats2half2_rn(a, b);
    return *(uint32_t*)&h;
}

#define LDSM4(r0, r1, r2, r3, addr) \
    asm volatile("ldmatrix.sync.aligned.m8n8.x4.shared.b16 {%0,%1,%2,%3}, [%4];" \
        : "=r"(r0), "=r"(r1), "=r"(r2), "=r"(r3) : "r"(addr))

#define LDSM4T(r0, r1, r2, r3, addr) \
    asm volatile("ldmatrix.sync.aligned.m8n8.x4.trans.shared.b16 {%0,%1,%2,%3}, [%4];" \
        : "=r"(r0), "=r"(r1), "=r"(r2), "=r"(r3) : "r"(addr))

#define CP16(dst, src) \
    asm volatile("cp.async.cg.shared.global [%0], [%1], 16;\n" :: "r"(dst), "l"(src))
#define CP_COMMIT() asm volatile("cp.async.commit_group;\n")
#define CP_WAIT0()  asm volatile("cp.async.wait_group 0;\n" ::: "memory")

// ---------------------------------------------------------------------------
__global__ void f2h(const float* __restrict__ in, __half* __restrict__ out_, int n4)
{
    int i = blockIdx.x * blockDim.x + threadIdx.x;
    if (i < n4) {
        float4 t = ((const float4*)in)[i];
        ((uint2*)out_)[i] = make_uint2(packh2(t.x, t.y), packh2(t.z, t.w));
    }
}

__global__ void f2h_s(const float* __restrict__ in, __half* __restrict__ out_,
                      int n4, int off)
{
    int i = blockIdx.x * blockDim.x + threadIdx.x;
    if (i < n4) {
        float4 t = ((const float4*)in)[i];
        int row = i >> 6, col4 = i & 63;
        ((uint2*)out_)[row * (KVS/4) + (off >> 2) + col4] =
            make_uint2(packh2(t.x, t.y), packh2(t.z, t.w));
    }
}

// ---------------------------------------------------------------------------
// Fused K|V projection GEMM (R15-proven 2-stage pipeline).
// ---------------------------------------------------------------------------
__global__ __launch_bounds__(256)
void gemm_kv(const __half* __restrict__ A, const __half* __restrict__ W,
             const float* __restrict__ b_k, const float* __restrict__ b_v,
             __half* __restrict__ Kout, __half* __restrict__ Vout, int M, int K)
{
    __shared__ uint32_t As[2][128][20];
    __shared__ uint32_t Bs[2][32][36];

    int tid = threadIdx.x;
    int lane = tid & 31, w = tid >> 5;
    int g = lane >> 2, tg = lane & 3;
    int wm = (w & 3) * 32, wn = (w >> 2) * 32;
    int m0 = blockIdx.y * 128, n0 = blockIdx.x * 64;

    int la  = lane & 15;
    int ha  = (lane >> 4) * 4;
    int lbk = (lane & 7) + ((lane >> 3) & 1) * 8;
    int hbn = (lane >> 4) * 4;

    uint32_t asb = (uint32_t)__cvta_generic_to_shared(&As[0][0][0]);
    uint32_t bsb = (uint32_t)__cvta_generic_to_shared(&Bs[0][0][0]);

    int ar = tid >> 2, ac4 = tid & 3;
    int br = tid >> 3, bc4 = tid & 7;

    auto issue = [&](int k0, int buf) {
        uint32_t ad = asb + buf * 128 * 20 * 4;
        uint32_t bd = bsb + buf * 32 * 36 * 4;
        CP16(ad + (ar * 20 + ac4 * 4) * 4,         A + (size_t)(m0 + ar) * K + k0 + ac4 * 8);
        CP16(ad + ((ar + 64) * 20 + ac4 * 4) * 4,  A + (size_t)(m0 + ar + 64) * K + k0 + ac4 * 8);
        CP16(bd + (br * 36 + bc4 * 4) * 4,         W + (size_t)(k0 + br) * KVS + n0 + bc4 * 8);
        CP_COMMIT();
    };

    float acc[2][4][4] = {};

    int niter = K / 32;
    issue(0, 0);

    for (int i = 0; i < niter; i++) {
        int cur = i & 1;
        CP_WAIT0();
        __syncthreads();
        if (i + 1 < niter) issue((i + 1) * 32, 1 - cur);

        uint32_t aoff = asb + cur * 128 * 20 * 4;
        uint32_t boff = bsb + cur * 32 * 36 * 4;

#pragma unroll
        for (int ks = 0; ks < 2; ks++) {
            uint32_t af[2][4], bf[4][2];
#pragma unroll
            for (int mt = 0; mt < 2; mt++) {
                uint32_t addr = aoff + ((wm + mt*16 + la) * 20 + ks*8 + ha) * 4;
                LDSM4(af[mt][0], af[mt][1], af[mt][2], af[mt][3], addr);
            }
#pragma unroll
            for (int ntp = 0; ntp < 2; ntp++) {
                uint32_t addr = boff + ((ks*16 + lbk) * 36 + wn/2 + ntp*8 + hbn) * 4;
                LDSM4T(bf[2*ntp][0], bf[2*ntp][1], bf[2*ntp+1][0], bf[2*ntp+1][1], addr);
            }
#pragma unroll
            for (int mt = 0; mt < 2; mt++)
#pragma unroll
                for (int nt = 0; nt < 4; nt++)
                    mma_f16(acc[mt][nt], af[mt], bf[nt]);
        }
    }

    bool isk = (n0 < KVC);
    const float* biasp = isk ? b_k : b_v;
    __half* Cp = isk ? Kout : Vout;
    int cbase = isk ? n0 : n0 - KVC;

#pragma unroll
    for (int mt = 0; mt < 2; mt++) {
        int r0 = m0 + wm + mt * 16 + g;
#pragma unroll
        for (int nt = 0; nt < 4; nt++) {
            int cl = cbase + wn + nt * 8 + tg * 2;
            float2 bb = *(const float2*)(biasp + cl);
            float2 v0 = make_float2(acc[mt][nt][0] + bb.x, acc[mt][nt][1] + bb.y);
            float2 v1 = make_float2(acc[mt][nt][2] + bb.x, acc[mt][nt][3] + bb.y);
            if (isk) {
                int pair = (cl & (HD - 1)) >> 1;
                float inv = powf(10000.0f, -(float)(2 * pair) / (float)HD);
                float sn0, cs0, sn1, cs1;
                sincosf((float)(r0 & (Tsz - 1)) * inv, &sn0, &cs0);
                sincosf((float)((r0 + 8) & (Tsz - 1)) * inv, &sn1, &cs1);
                float e0 = v0.x, o0 = v0.y;
                v0.x = e0 * cs0 - o0 * sn0;  v0.y = e0 * sn0 + o0 * cs0;
                float e1 = v1.x, o1 = v1.y;
                v1.x = e1 * cs1 - o1 * sn1;  v1.y = e1 * sn1 + o1 * cs1;
            }
            *(uint32_t*)(Cp + (size_t)r0 * KVC + cl)       = packh2(v0.x, v0.y);
            *(uint32_t*)(Cp + (size_t)(r0 + 8) * KVC + cl) = packh2(v1.x, v1.y);
        }
    }
}

// ---------------------------------------------------------------------------
// WIDE fp16 GEMM, CTA tile 128x128 (R15-proven 2-stage pipeline).
// ---------------------------------------------------------------------------
template<bool DO_ROPE, bool HALF_OUT>
__global__ __launch_bounds__(256, 2)
void gemm_w(const __half* __restrict__ A, const __half* __restrict__ W,
            const float* __restrict__ bias, void* __restrict__ Cout,
            int M, int K, int N, float oscale)
{
    __shared__ uint32_t As[2][128][20];
    __shared__ uint32_t Bs[2][32][68];

    int tid = threadIdx.x;
    int lane = tid & 31, w = tid >> 5;
    int g = lane >> 2, tg = lane & 3;
    int wm = (w & 3) * 32, wn = (w >> 2) * 64;
    int m0 = blockIdx.y * 128, n0 = blockIdx.x * 128;

    int la  = lane & 15;
    int ha  = (lane >> 4) * 4;
    int lbk = (lane & 7) + ((lane >> 3) & 1) * 8;
    int hbn = (lane >> 4) * 4;

    uint32_t asb = (uint32_t)__cvta_generic_to_shared(&As[0][0][0]);
    uint32_t bsb = (uint32_t)__cvta_generic_to_shared(&Bs[0][0][0]);

    int ar = tid >> 2, ac4 = tid & 3;
    int br = tid >> 4, bc4 = tid & 15;

    auto issue = [&](int k0, int buf) {
        uint32_t ad = asb + buf * 128 * 20 * 4;
        uint32_t bd = bsb + buf * 32 * 68 * 4;
        CP16(ad + (ar * 20 + ac4 * 4) * 4,          A + (size_t)(m0 + ar) * K + k0 + ac4 * 8);
        CP16(ad + ((ar + 64) * 20 + ac4 * 4) * 4,   A + (size_t)(m0 + ar + 64) * K + k0 + ac4 * 8);
        CP16(bd + (br * 68 + bc4 * 4) * 4,          W + (size_t)(k0 + br) * N + n0 + bc4 * 8);
        CP16(bd + ((br + 16) * 68 + bc4 * 4) * 4,   W + (size_t)(k0 + br + 16) * N + n0 + bc4 * 8);
        CP_COMMIT();
    };

    float acc[2][8][4] = {};

    int niter = K / 32;
    issue(0, 0);

    for (int i = 0; i < niter; i++) {
        int cur = i & 1;
        CP_WAIT0();
        __syncthreads();
        if (i + 1 < niter) issue((i + 1) * 32, 1 - cur);

        uint32_t aoff = asb + cur * 128 * 20 * 4;
        uint32_t boff = bsb + cur * 32 * 68 * 4;

#pragma unroll
        for (int ks = 0; ks < 2; ks++) {
            uint32_t af[2][4], bf[8][2];
#pragma unroll
            for (int mt = 0; mt < 2; mt++) {
                uint32_t addr = aoff + ((wm + mt*16 + la) * 20 + ks*8 + ha) * 4;
                LDSM4(af[mt][0], af[mt][1], af[mt][2], af[mt][3], addr);
            }
#pragma unroll
            for (int ntp = 0; ntp < 4; ntp++) {
                uint32_t addr = boff + ((ks*16 + lbk) * 68 + wn/2 + ntp*8 + hbn) * 4;
                LDSM4T(bf[2*ntp][0], bf[2*ntp][1], bf[2*ntp+1][0], bf[2*ntp+1][1], addr);
            }
#pragma unroll
            for (int mt = 0; mt < 2; mt++)
#pragma unroll
                for (int nt = 0; nt < 8; nt++)
                    mma_f16(acc[mt][nt], af[mt], bf[nt]);
        }
    }

#pragma unroll
    for (int mt = 0; mt < 2; mt++) {
        int r0 = m0 + wm + mt * 16 + g;
#pragma unroll
        for (int nt = 0; nt < 8; nt++) {
            int c = n0 + wn + nt * 8 + tg * 2;
            float2 bb = *(const float2*)(bias + c);
            float2 v0 = make_float2(acc[mt][nt][0] + bb.x, acc[mt][nt][1] + bb.y);
            float2 v1 = make_float2(acc[mt][nt][2] + bb.x, acc[mt][nt][3] + bb.y);
            if (DO_ROPE) {
                int pair = (c & (HD - 1)) >> 1;
                float inv = powf(10000.0f, -(float)(2 * pair) / (float)HD);
                float sn0, cs0, sn1, cs1;
                sincosf((float)(r0 & (Tsz - 1)) * inv, &sn0, &cs0);
                sincosf((float)((r0 + 8) & (Tsz - 1)) * inv, &sn1, &cs1);
                float e0 = v0.x, o0 = v0.y;
                v0.x = e0 * cs0 - o0 * sn0;  v0.y = e0 * sn0 + o0 * cs0;
                float e1 = v1.x, o1 = v1.y;
                v1.x = e1 * cs1 - o1 * sn1;  v1.y = e1 * sn1 + o1 * cs1;
            }
            v0.x *= oscale; v0.y *= oscale; v1.x *= oscale; v1.y *= oscale;
            if (HALF_OUT) {
                __half* C = (__half*)Cout;
                *(uint32_t*)(C + (size_t)r0 * N + c)       = packh2(v0.x, v0.y);
                *(uint32_t*)(C + (size_t)(r0 + 8) * N + c) = packh2(v1.x, v1.y);
            } else {
                float* C = (float*)Cout;
                *(float2*)(C + (size_t)r0 * N + c)       = v0;
                *(float2*)(C + (size_t)(r0 + 8) * N + c) = v1;
            }
        }
    }
}

// ---------------------------------------------------------------------------
// Flash attention v4 (R15-proven, 2-stage). bbase selects the batch.
// CTA: 64 q-rows x 1 head, 8 warps = 4(m,16 rows)x2(n,32 keys).
// ---------------------------------------------------------------------------
__global__ __launch_bounds__(256, 2)
void attn_f16(const __half* __restrict__ q, const __half* __restrict__ k,
              const __half* __restrict__ v, __half* __restrict__ o, int bbase)
{
    extern __shared__ uint32_t smu[];
    uint32_t* Qs = smu;                    // [64][36]
    uint32_t* Ks = smu + 64*36;            // [2][64][36] row=key
    uint32_t* Vs = smu + 64*36 + 2*64*36;  // [2][64][36] row=key

    int b  = bbase;
    int h  = blockIdx.y;
    int qb = gridDim.x - 1 - blockIdx.x;   // heavy blocks first
    int q0 = qb * QB;
    int kvh = h >> 2;

    int tid = threadIdx.x;
    int lane = tid & 31, w = tid >> 5;
    int g = lane >> 2, tg = lane & 3;
    int wm = (w >> 1) * 16;    // warp row origin (0,16,32,48)
    int wn = w & 1;            // key half

    int la  = lane & 15;
    int ha  = (lane >> 4) * 4;
    int lb  = (lane & 7) + (lane >> 4) * 8;
    int hb  = ((lane >> 3) & 1) * 4;
    int lbk = (lane & 7) + ((lane >> 3) & 1) * 8;
    int hbn = (lane >> 4) * 4;

    uint32_t qsb = (uint32_t)__cvta_generic_to_shared(Qs);
    uint32_t ksb = (uint32_t)__cvta_generic_to_shared(Ks);
    uint32_t vsb = (uint32_t)__cvta_generic_to_shared(Vs);

    // Q tile via cp.async
    {
        const __half* qbase = q + (size_t)(b * Tsz + q0) * Csz + h * HD;
#pragma unroll
        for (int p = 0; p < 2; p++) {
            int idx = tid + p * 256;
            int r = idx >> 3, c4 = idx & 7;
            CP16(qsb + (r * 36 + c4 * 4) * 4, qbase + (size_t)r * Csz + c4 * 8);
        }
        CP_COMMIT();
    }

    float mrun[2], lrun[2];
    float oacc[8][4] = {};
#pragma unroll
    for (int ri = 0; ri < 2; ri++) { mrun[ri] = -1e30f; lrun[ri] = 0.f; }

    auto issue_kv = [&](int kb, int buf) {
        const __half* kp = k + (size_t)(b * Tsz + kb * 64) * KVC + kvh * HD;
        const __half* vp = v + (size_t)(b * Tsz + kb * 64) * KVC + kvh * HD;
        uint32_t kdst = ksb + buf * 64 * 36 * 4;
        uint32_t vdst = vsb + buf * 64 * 36 * 4;
#pragma unroll
        for (int p = 0; p < 2; p++) {
            int idx = tid + p * 256;
            int key = idx >> 3, c4 = idx & 7;
            CP16(kdst + (key * 36 + c4 * 4) * 4, kp + (size_t)key * KVC + c4 * 8);
            CP16(vdst + (key * 36 + c4 * 4) * 4, vp + (size_t)key * KVC + c4 * 8);
        }
        CP_COMMIT();
    };

    issue_kv(0, 0);

    for (int kb = 0; kb <= qb; kb++) {
        int cur = kb & 1;
        CP_WAIT0();
        __syncthreads();   // the ONLY sync per tile
        if (kb < qb) issue_kv(kb + 1, 1 - cur);

        uint32_t koff = ksb + cur * 64 * 36 * 4;
        uint32_t voff = vsb + cur * 64 * 36 * 4;

        // S = Q K^T : 16 rows x 32 keys (warp's half)
        float s[4][4] = {};
#pragma unroll
        for (int ks = 0; ks < 4; ks++) {
            uint32_t af[4], bf[4][2];
            {
                uint32_t addr = qsb + ((wm + la) * 36 + ks*8 + ha) * 4;
                LDSM4(af[0], af[1], af[2], af[3], addr);
            }
#pragma unroll
            for (int ntp = 0; ntp < 2; ntp++) {
                uint32_t addr = koff + ((wn*32 + ntp*16 + lb) * 36 + ks*8 + hb) * 4;
                LDSM4(bf[2*ntp][0], bf[2*ntp][1], bf[2*ntp+1][0], bf[2*ntp+1][1], addr);
            }
#pragma unroll
            for (int nt = 0; nt < 4; nt++)
                mma_f16(s[nt], af, bf[nt]);
        }

        // causal mask (diagonal tile only)
        if (kb == qb) {
            int row0 = q0 + wm + g;
#pragma unroll
            for (int nt = 0; nt < 4; nt++) {
                int col = kb * 64 + wn * 32 + nt * 8 + 2 * tg;
                if (col     > row0    ) s[nt][0] = -1e30f;
                if (col + 1 > row0    ) s[nt][1] = -1e30f;
                if (col     > row0 + 8) s[nt][2] = -1e30f;
                if (col + 1 > row0 + 8) s[nt][3] = -1e30f;
            }
        }

        // warp-local streaming softmax over this half's 32 keys
#pragma unroll
        for (int ri = 0; ri < 2; ri++) {
            float mx = -1e30f;
#pragma unroll
            for (int nt = 0; nt < 4; nt++) {
                mx = fmaxf(mx, s[nt][2*ri]);
                mx = fmaxf(mx, s[nt][2*ri+1]);
            }
            mx = fmaxf(mx, __shfl_xor_sync(0xffffffffu, mx, 1));
            mx = fmaxf(mx, __shfl_xor_sync(0xffffffffu, mx, 2));
            float mnew = fmaxf(mrun[ri], mx);
            float corr = __expf(mrun[ri] - mnew);
            float sum = 0.f;
#pragma unroll
            for (int nt = 0; nt < 4; nt++) {
                float p0 = __expf(s[nt][2*ri]   - mnew);
                float p1 = __expf(s[nt][2*ri+1] - mnew);
                s[nt][2*ri] = p0; s[nt][2*ri+1] = p1;
                sum += p0 + p1;
            }
            sum += __shfl_xor_sync(0xffffffffu, sum, 1);
            sum += __shfl_xor_sync(0xffffffffu, sum, 2);
            lrun[ri] = lrun[ri] * corr + sum;
            mrun[ri] = mnew;
#pragma unroll
            for (int nt = 0; nt < 8; nt++) {
                oacc[nt][2*ri]   *= corr;
                oacc[nt][2*ri+1] *= corr;
            }
        }

        // O_partial += P V : P in registers; V via ldmatrix.trans
#pragma unroll
        for (int ks = 0; ks < 2; ks++) {
            uint32_t af[4], bf[8][2];
            af[0] = packh2(s[2*ks  ][0], s[2*ks  ][1]);
            af[1] = packh2(s[2*ks  ][2], s[2*ks  ][3]);
            af[2] = packh2(s[2*ks+1][0], s[2*ks+1][1]);
            af[3] = packh2(s[2*ks+1][2], s[2*ks+1][3]);
#pragma unroll
            for (int ntp = 0; ntp < 4; ntp++) {
                uint32_t addr = voff + ((wn*32 + ks*16 + lbk) * 36 + ntp*8 + hbn) * 4;
                LDSM4T(bf[2*ntp][0], bf[2*ntp][1], bf[2*ntp+1][0], bf[2*ntp+1][1], addr);
            }
#pragma unroll
            for (int nt = 0; nt < 8; nt++)
                mma_f16(oacc[nt], af, bf[nt]);
        }
    }

    // ---- final cross-half merge (once) ----
    __syncthreads();                        // loop done; reuse smem
    float*  Osm = (float*)smu;              // [64][68]
    float2* ml  = (float2*)(smu + 64*68);   // [64]

    if (wn == 0) {
#pragma unroll
        for (int ri = 0; ri < 2; ri++) {
            int rl = wm + ri*8 + g;
            if (tg == 0) ml[rl] = make_float2(mrun[ri], lrun[ri]);
#pragma unroll
            for (int nt = 0; nt < 8; nt++)
                *(float2*)&Osm[rl * 68 + nt*8 + 2*tg] =
                    make_float2(oacc[nt][2*ri], oacc[nt][2*ri+1]);
        }
    }
    __syncthreads();

    if (wn == 1) {
        __half* obase = o + (size_t)(b * Tsz + q0) * Csz + h * HD;
#pragma unroll
        for (int ri = 0; ri < 2; ri++) {
            int rl = wm + ri*8 + g;
            float2 other = ml[rl];
            float mnew = fmaxf(mrun[ri], other.x);
            float c1 = __expf(mrun[ri] - mnew);
            float c0 = __expf(other.x  - mnew);
            float l = lrun[ri] * c1 + other.y * c0;
            float inv = 1.0f / l;
#pragma unroll
            for (int nt = 0; nt < 8; nt++) {
                float2 o0 = *(float2*)&Osm[rl * 68 + nt*8 + 2*tg];
                float r0 = (oacc[nt][2*ri]   * c1 + o0.x * c0) * inv;
                float r1 = (oacc[nt][2*ri+1] * c1 + o0.y * c0) * inv;
                *(uint32_t*)(obase + (size_t)rl * Csz + nt*8 + 2*tg) = packh2(r0, r1);
            }
        }
    }
}

// ---------------------------------------------------------------------------
extern "C" void kernel_launch(void* const* d_in, const int* in_sizes, int n_in,
                              void* d_out, int out_size)
{
    const float* x   = (const float*)d_in[0];
    const float* w_q = (const float*)d_in[1];
    const float* b_q = (const float*)d_in[2];
    const float* w_k = (const float*)d_in[3];
    const float* b_k = (const float*)d_in[4];
    const float* w_v = (const float*)d_in[5];
    const float* b_v = (const float*)d_in[6];
    const float* w_o = (const float*)d_in[7];
    const float* b_o = (const float*)d_in[8];
    float* out = (float*)d_out;

    __half *xh, *wqh, *wkvh, *woh, *q, *k, *v, *ao;
    cudaGetSymbolAddress((void**)&xh,   g_xh);
    cudaGetSymbolAddress((void**)&wqh,  g_wqh);
    cudaGetSymbolAddress((void**)&wkvh, g_wkvh);
    cudaGetSymbolAddress((void**)&woh,  g_woh);
    cudaGetSymbolAddress((void**)&q,    g_q);
    cudaGetSymbolAddress((void**)&k,    g_k);
    cudaGetSymbolAddress((void**)&v,    g_v);
    cudaGetSymbolAddress((void**)&ao,   g_ao);

    cudaStream_t s1 = g_str.s1, s2 = g_str.s2;
    int attn_smem = (64 + 2*64 + 2*64) * 36 * 4;   // 46080
    cudaFuncSetAttribute(attn_f16, cudaFuncAttributeMaxDynamicSharedMemorySize, attn_smem);

    // legacy: convert x, fork; then O weights
    f2h<<<(Mrows*Csz/4 + 255)/256, 256>>>(x, xh, Mrows*Csz/4);
    cudaEventRecord(g_str.eA, 0);
    f2h<<<(Csz*Csz/4 + 255)/256, 256>>>(w_o, woh, Csz*Csz/4);
    cudaEventRecord(g_str.eW, 0);

    // branch 1 (s1): Q projection
    cudaStreamWaitEvent(s1, g_str.eA, 0);
    f2h<<<(Csz*Csz/4 + 255)/256, 256, 0, s1>>>(w_q, wqh, Csz*Csz/4);
    gemm_w<true , true ><<<dim3(Csz/128, Mrows/128), 256, 0, s1>>>(
        xh, wqh, b_q, q, Mrows, Csz, Csz, 0.125f);
    cudaEventRecord(g_str.e1, s1);

    // branch 2 (s2): fused K|V projection
    cudaStreamWaitEvent(s2, g_str.eA, 0);
    f2h_s<<<(Csz*KVC/4 + 255)/256, 256, 0, s2>>>(w_k, wkvh, Csz*KVC/4, 0);
    f2h_s<<<(Csz*KVC/4 + 255)/256, 256, 0, s2>>>(w_v, wkvh, Csz*KVC/4, KVC);
    gemm_kv<<<dim3(KVS/64, Mrows/128), 256, 0, s2>>>(
        xh, wkvh, b_k, b_v, k, v, Mrows, Csz);
    cudaEventRecord(g_str.e2, s2);

    // legacy: attention batch 0 -> O GEMM rows [0, 2048)
    cudaStreamWaitEvent(0, g_str.e1, 0);
    cudaStreamWaitEvent(0, g_str.e2, 0);
    attn_f16<<<dim3(Tsz/QB, NH, 1), 256, attn_smem>>>(q, k, v, ao, 0);
    gemm_w<false, false><<<dim3(Csz/128, (Mrows/2)/128), 256>>>(
        ao, woh, b_o, out, Mrows, Csz, Csz, 1.0f);

    // s1: attention batch 1 -> O GEMM rows [2048, 4096)
    cudaStreamWaitEvent(s1, g_str.e2, 0);
    cudaStreamWaitEvent(s1, g_str.eW, 0);
    attn_f16<<<dim3(Tsz/QB, NH, 1), 256, attn_smem, s1>>>(q, k, v, ao, 1);
    gemm_w<false, false><<<dim3(Csz/128, (Mrows/2)/128), 256, 0, s1>>>(
        ao + (size_t)(Mrows/2) * Csz, woh, b_o,
        out + (size_t)(Mrows/2) * Csz, Mrows, Csz, Csz, 1.0f);
    cudaEventRecord(g_str.e3, s1);

    // join s1 back to legacy so the graph's output is fully ordered
    cudaStreamWaitEvent(0, g_str.e3, 0);
}